// round 3
// baseline (speedup 1.0000x reference)
#include <cuda_runtime.h>
#include <cstdint>

#define NMAX 100000
#define INDIM 256

// ---------------- device scratch ----------------
__device__ float g_h [NMAX * 64];
__device__ float g_m [NMAX * 64];
__device__ float g_x1[NMAX * 128];
__device__ float g_x2[NMAX * 64];
__device__ float g_deg[NMAX];

// ---------------- f32x2 packed math helpers ----------------
__device__ __forceinline__ unsigned long long fma2(unsigned long long a,
                                                   unsigned long long b,
                                                   unsigned long long c) {
    unsigned long long d;
    asm("fma.rn.f32x2 %0, %1, %2, %3;" : "=l"(d) : "l"(a), "l"(b), "l"(c));
    return d;
}
__device__ __forceinline__ float2 unpack2(unsigned long long v) {
    float2 f;
    asm("mov.b64 {%0,%1}, %2;" : "=f"(f.x), "=f"(f.y) : "l"(v));
    return f;
}

// ---------------- small utility kernels ----------------
__global__ void zero4_kernel(float4* __restrict__ p, int n4) {
    int i = blockIdx.x * blockDim.x + threadIdx.x;
    if (i < n4) p[i] = make_float4(0.f, 0.f, 0.f, 0.f);
}

__global__ void degree_kernel(const int* __restrict__ dst, float* __restrict__ deg, int E) {
    int e = blockIdx.x * blockDim.x + threadIdx.x;
    if (e < E) atomicAdd(&deg[dst[e]], 1.0f);
}

__global__ void invdeg_kernel(float* __restrict__ deg, int n) {
    int i = blockIdx.x * blockDim.x + threadIdx.x;
    if (i < n) deg[i] = 1.0f / fmaxf(deg[i], 1.0f);
}

// ---------------- scatter-add of 64-float messages ----------------
__global__ void scatter64_kernel(const float4* __restrict__ h,
                                 const int* __restrict__ src,
                                 const int* __restrict__ dst,
                                 float4* __restrict__ acc,
                                 int E) {
    int i = blockIdx.x * blockDim.x + threadIdx.x;
    int total = E * 16;
    if (i >= total) return;
    int e = i >> 4;
    int j = i & 15;
    int s = __ldg(&src[e]);
    int d = __ldg(&dst[e]);
    float4 v = __ldg(&h[(size_t)s * 16 + j]);
    float* p = (float*)&acc[(size_t)d * 16 + j];
    asm volatile("red.global.add.v4.f32 [%0], {%1,%2,%3,%4};"
                 :: "l"(p), "f"(v.x), "f"(v.y), "f"(v.z), "f"(v.w) : "memory");
}

// ---------------- concat-GEMM, pack-free f32x2 inner loop ----------------
// C = relu?( [A1 | A2*invdeg] @ W + bias )
// A1:[n,K1]  A2:[n,K2]  W:[(K1+K2),OUT] row-major
// Accumulators pair two adjacent M-rows per f32x2 lane; W tile is stored
// duplicated in shared so both operands come ready-packed from LDS.128.
template<int K1, int K2, int OUT, bool RELU>
__global__ __launch_bounds__(256, 2)
void gemm_cat3(const float* __restrict__ A1,
               const float* __restrict__ A2,
               const float* __restrict__ invdeg,
               const float* __restrict__ W,
               const float* __restrict__ bias,
               float* __restrict__ C, int n)
{
    constexpr int K   = K1 + K2;
    constexpr int BM  = 128;
    constexpr int BK  = 32;
    constexpr int TN  = OUT / 16;            // 4 (OUT=64) or 8 (OUT=128)
    constexpr int LDA = (OUT == 128) ? BM : (BM + 4);  // smem budget for OUT=128

    static_assert(K % BK == 0, "K multiple of BK");
    static_assert(K1 % 4 == 0, "K1 multiple of 4");

    __shared__ float As [BK][LDA];       // k-major A tile (rows contiguous)
    __shared__ float Ws2[BK][2 * OUT];   // duplicated W tile

    const int tid  = threadIdx.x;
    const int tx   = tid & 15;           // 16 col groups
    const int ty   = tid >> 4;           // 16 row groups (8 rows each)
    const int row0 = blockIdx.x * BM;
    const int B    = ty * 8;

    unsigned long long acc[4][TN];       // pair p = rows (B+2p, B+2p+1)
#pragma unroll
    for (int p = 0; p < 4; p++)
#pragma unroll
        for (int j = 0; j < TN; j++) acc[p][j] = 0ull;

    for (int kt = 0; kt < K; kt += BK) {
        // ---- A tile: 1024 float4 loads, transposed (k-major) store ----
#pragma unroll
        for (int p = 0; p < 4; p++) {
            int idx  = tid + p * 256;
            int r    = idx >> 3;
            int kc   = idx & 7;
            int grow = row0 + r;
            int gk   = kt + kc * 4;
            float4 v = make_float4(0.f, 0.f, 0.f, 0.f);
            if (grow < n) {
                if (K2 == 0 || gk < K1) {
                    v = *(const float4*)&A1[(size_t)grow * K1 + gk];
                } else {
                    v = *(const float4*)&A2[(size_t)grow * K2 + (gk - K1)];
                    float s = __ldg(&invdeg[grow]);
                    v.x *= s; v.y *= s; v.z *= s; v.w *= s;
                }
            }
            As[kc * 4 + 0][r] = v.x;
            As[kc * 4 + 1][r] = v.y;
            As[kc * 4 + 2][r] = v.z;
            As[kc * 4 + 3][r] = v.w;
        }
        // ---- W tile, duplicated: Ws2[k][2c]=Ws2[k][2c+1]=W[k][c] ----
#pragma unroll
        for (int idx = tid; idx < BK * OUT; idx += 256) {
            int k = idx / OUT;
            int c = idx % OUT;
            float v = W[(size_t)(kt + k) * OUT + c];
            float2 d2 = make_float2(v, v);
            *(float2*)&Ws2[k][2 * c] = d2;
        }
        __syncthreads();

#pragma unroll 8
        for (int k = 0; k < BK; k++) {
            const ulonglong2* ap = (const ulonglong2*)&As[k][B];
            ulonglong2 a01 = ap[0];                 // rows (B,B+1),(B+2,B+3)
            ulonglong2 a45 = ap[1];                 // rows (B+4,B+5),(B+6,B+7)
            unsigned long long apair[4] = {a01.x, a01.y, a45.x, a45.y};

            unsigned long long bdup[TN];
            const ulonglong2* bp = (const ulonglong2*)&Ws2[k][2 * tx * TN];
#pragma unroll
            for (int j2 = 0; j2 < TN / 2; j2++) {
                ulonglong2 b = bp[j2];
                bdup[2 * j2]     = b.x;
                bdup[2 * j2 + 1] = b.y;
            }
#pragma unroll
            for (int p = 0; p < 4; p++)
#pragma unroll
                for (int j = 0; j < TN; j++)
                    acc[p][j] = fma2(apair[p], bdup[j], acc[p][j]);
        }
        __syncthreads();
    }

    // ---- epilogue: unpack row pairs, vector stores ----
    float bv[TN];
#pragma unroll
    for (int j = 0; j < TN; j++) bv[j] = bias[tx * TN + j];

#pragma unroll
    for (int p = 0; p < 4; p++) {
        int r0 = row0 + B + 2 * p;
        float v0[TN], v1[TN];
#pragma unroll
        for (int j = 0; j < TN; j++) {
            float2 f = unpack2(acc[p][j]);
            float a = f.x + bv[j];
            float b = f.y + bv[j];
            if (RELU) { a = fmaxf(a, 0.f); b = fmaxf(b, 0.f); }
            v0[j] = a; v1[j] = b;
        }
        if (r0 < n) {
#pragma unroll
            for (int j4 = 0; j4 < TN / 4; j4++)
                *(float4*)&C[(size_t)r0 * OUT + tx * TN + j4 * 4] =
                    make_float4(v0[j4*4], v0[j4*4+1], v0[j4*4+2], v0[j4*4+3]);
        }
        if (r0 + 1 < n) {
#pragma unroll
            for (int j4 = 0; j4 < TN / 4; j4++)
                *(float4*)&C[(size_t)(r0 + 1) * OUT + tx * TN + j4 * 4] =
                    make_float4(v1[j4*4], v1[j4*4+1], v1[j4*4+2], v1[j4*4+3]);
        }
    }
}

// ---------------- head: out = relu(x2 @ Wl1 + bl1) @ Wl2 + bl2 ----------------
__global__ void head_kernel(const float* __restrict__ x2,
                            const float* __restrict__ Wl1,
                            const float* __restrict__ bl1,
                            const float* __restrict__ Wl2,
                            const float* __restrict__ bl2,
                            float* __restrict__ out, int n)
{
    int gtid = blockIdx.x * blockDim.x + threadIdx.x;
    int row  = gtid >> 5;
    int lane = gtid & 31;
    if (row >= n) return;

    const float* xr = x2 + (size_t)row * 64;
    float acc = 0.f;
#pragma unroll
    for (int k = 0; k < 64; k++)
        acc = fmaf(__ldg(&xr[k]), __ldg(&Wl1[k * 32 + lane]), acc);
    float h = fmaxf(acc + __ldg(&bl1[lane]), 0.f);
    float p = h * __ldg(&Wl2[lane]);
#pragma unroll
    for (int off = 16; off; off >>= 1)
        p += __shfl_down_sync(0xffffffffu, p, off);
    if (lane == 0) out[row] = p + __ldg(&bl2[0]);
}

// ---------------- launch ----------------
extern "C" void kernel_launch(void* const* d_in, const int* in_sizes, int n_in,
                              void* d_out, int out_size)
{
    const float* x    = (const float*)d_in[0];
    const int*   ei   = (const int*)  d_in[1];
    const float* W1a  = (const float*)d_in[3];
    const float* b1a  = (const float*)d_in[4];
    const float* W1b  = (const float*)d_in[5];
    const float* b1b  = (const float*)d_in[6];
    const float* W2a  = (const float*)d_in[7];
    const float* b2a  = (const float*)d_in[8];
    const float* W2b  = (const float*)d_in[9];
    const float* b2b  = (const float*)d_in[10];
    const float* Wl1  = (const float*)d_in[11];
    const float* bl1  = (const float*)d_in[12];
    const float* Wl2  = (const float*)d_in[13];
    const float* bl2  = (const float*)d_in[14];
    float* out = (float*)d_out;

    const int N = in_sizes[0] / INDIM;
    const int E = in_sizes[1] / 2;
    const int* src = ei;
    const int* dst = ei + E;

    float *h, *m, *x1, *x2, *deg;
    cudaGetSymbolAddress((void**)&h,   g_h);
    cudaGetSymbolAddress((void**)&m,   g_m);
    cudaGetSymbolAddress((void**)&x1,  g_x1);
    cudaGetSymbolAddress((void**)&x2,  g_x2);
    cudaGetSymbolAddress((void**)&deg, g_deg);

    const int T = 256;
    auto blocks = [](long long work, int t) { return (int)((work + t - 1) / t); };
    const int gemm_grid = blocks(N, 128);

    // degree (shared by both layers)
    zero4_kernel<<<blocks((N + 3) / 4, T), T>>>((float4*)deg, (N + 3) / 4);
    degree_kernel<<<blocks(E, T), T>>>(dst, deg, E);
    invdeg_kernel<<<blocks(N, T), T>>>(deg, N);

    // ---- layer 1 ----
    zero4_kernel<<<blocks((long long)N * 16, T), T>>>((float4*)m, N * 16);
    gemm_cat3<256, 0, 64, false><<<gemm_grid, 256>>>(x, nullptr, nullptr, W1a, b1a, h, N);
    scatter64_kernel<<<blocks((long long)E * 16, T), T>>>((const float4*)h, src, dst, (float4*)m, E);
    gemm_cat3<256, 64, 128, true><<<gemm_grid, 256>>>(x, m, deg, W1b, b1b, x1, N);

    // ---- layer 2 ----
    zero4_kernel<<<blocks((long long)N * 16, T), T>>>((float4*)m, N * 16);
    gemm_cat3<128, 0, 64, false><<<gemm_grid, 256>>>(x1, nullptr, nullptr, W2a, b2a, h, N);
    scatter64_kernel<<<blocks((long long)E * 16, T), T>>>((const float4*)h, src, dst, (float4*)m, E);
    gemm_cat3<128, 64, 64, true><<<gemm_grid, 256>>>(x1, m, deg, W2b, b2b, x2, N);

    // ---- head ----
    head_kernel<<<blocks((long long)N * 32, T), T>>>(x2, Wl1, bl1, Wl2, bl2, out, N);
}

// round 4
// speedup vs baseline: 1.6227x; 1.6227x over previous
#include <cuda_runtime.h>
#include <cuda_fp16.h>
#include <cstdint>

#define NMAX 100000
#define INDIM 256

// ---------------- device scratch ----------------
__device__ __half g_h2[NMAX * 64];   // fp16 messages
__device__ float  g_m [NMAX * 64];   // fp32 aggregation accumulator
__device__ float  g_x1[NMAX * 128];
__device__ float  g_x2[NMAX * 64];
__device__ float  g_deg[NMAX];

// ---------------- f32x2 packed math helpers ----------------
__device__ __forceinline__ unsigned long long pack2(float lo, float hi) {
    unsigned long long r;
    asm("mov.b64 %0, {%1,%2};" : "=l"(r) : "f"(lo), "f"(hi));
    return r;
}
__device__ __forceinline__ unsigned long long fma2(unsigned long long a,
                                                   unsigned long long b,
                                                   unsigned long long c) {
    unsigned long long d;
    asm("fma.rn.f32x2 %0, %1, %2, %3;" : "=l"(d) : "l"(a), "l"(b), "l"(c));
    return d;
}
__device__ __forceinline__ float2 unpack2(unsigned long long v) {
    float2 f;
    asm("mov.b64 {%0,%1}, %2;" : "=f"(f.x), "=f"(f.y) : "l"(v));
    return f;
}

// ---------------- small utility kernels ----------------
__global__ void zero4_kernel(float4* __restrict__ p, int n4) {
    int i = blockIdx.x * blockDim.x + threadIdx.x;
    if (i < n4) p[i] = make_float4(0.f, 0.f, 0.f, 0.f);
}

__global__ void degree_kernel(const int* __restrict__ dst, float* __restrict__ deg, int E) {
    int e = blockIdx.x * blockDim.x + threadIdx.x;
    if (e < E) atomicAdd(&deg[dst[e]], 1.0f);
}

__global__ void invdeg_kernel(float* __restrict__ deg, int n) {
    int i = blockIdx.x * blockDim.x + threadIdx.x;
    if (i < n) deg[i] = 1.0f / fmaxf(deg[i], 1.0f);
}

// ---------------- scatter-add: fp16 gather, fp32 red accumulate ----------------
__global__ void scatter64_h_kernel(const uint2* __restrict__ h2u,  // [n][16] x 4 halves
                                   const int* __restrict__ src,
                                   const int* __restrict__ dst,
                                   float4* __restrict__ acc,       // [n][16] float4
                                   int E) {
    int i = blockIdx.x * blockDim.x + threadIdx.x;
    int total = E * 16;
    if (i >= total) return;
    int e = i >> 4;
    int j = i & 15;
    int s = __ldg(&src[e]);
    int d = __ldg(&dst[e]);
    uint2 raw = __ldg(&h2u[(size_t)s * 16 + j]);
    __half2 h0 = *(__half2*)&raw.x;
    __half2 h1 = *(__half2*)&raw.y;
    float2 f0 = __half22float2(h0);
    float2 f1 = __half22float2(h1);
    float* p = (float*)&acc[(size_t)d * 16 + j];
    asm volatile("red.global.add.v4.f32 [%0], {%1,%2,%3,%4};"
                 :: "l"(p), "f"(f0.x), "f"(f0.y), "f"(f1.x), "f"(f1.y) : "memory");
}

// ---------------- concat-GEMM, row-major smem A, reg-prefetch pipeline ----------
// C = act( [A1 | A2*invdeg] @ W + bias ), optionally emitted as fp16
template<int K1, int K2, int OUT, bool RELU, bool HALF_OUT>
__global__ __launch_bounds__(256, 2)
void gemm_cat4(const float* __restrict__ A1,
               const float* __restrict__ A2,
               const float* __restrict__ invdeg,
               const float* __restrict__ W,
               const float* __restrict__ bias,
               float* __restrict__ Cf,
               __half* __restrict__ Ch, int n)
{
    constexpr int K      = K1 + K2;
    constexpr int BM     = 128;
    constexpr int BK     = 32;
    constexpr int TN     = OUT / 16;        // 4 or 8
    constexpr int NP     = TN / 2;          // f32x2 accum pairs (cols)
    constexpr int NSTAGE = K / BK;
    constexpr int WREG   = (BK * OUT) / (256 * 4);  // float4 W loads per thread

    static_assert(K % BK == 0, "");
    static_assert(K1 % 4 == 0, "");

    __shared__ float As[BM][BK];      // row-major: 128B rows, conflict-free STS.128
    __shared__ float Ws[BK][OUT];

    const int tid  = threadIdx.x;
    const int tx   = tid & 15;
    const int ty   = tid >> 4;
    const int row0 = blockIdx.x * BM;
    const int B    = ty * 8;

    // decode this thread's tile-load coordinates once
    int ar[4], akc[4];
#pragma unroll
    for (int p = 0; p < 4; p++) {
        int idx = tid + p * 256;
        ar[p]  = idx >> 3;     // row 0..127
        akc[p] = idx & 7;      // k-chunk (float4)
    }

    unsigned long long acc[8][NP];
#pragma unroll
    for (int i = 0; i < 8; i++)
#pragma unroll
        for (int j = 0; j < NP; j++) acc[i][j] = 0ull;

    float4 pa[4];
    float4 pw[WREG];

    auto loadA = [&](int kt) {
#pragma unroll
        for (int p = 0; p < 4; p++) {
            int grow = row0 + ar[p];
            int gk   = kt + akc[p] * 4;
            float4 v = make_float4(0.f, 0.f, 0.f, 0.f);
            if (grow < n) {
                if (K2 == 0 || gk < K1) {
                    v = *(const float4*)&A1[(size_t)grow * K1 + gk];
                } else {
                    v = *(const float4*)&A2[(size_t)grow * K2 + (gk - K1)];
                    float s = __ldg(&invdeg[grow]);
                    v.x *= s; v.y *= s; v.z *= s; v.w *= s;
                }
            }
            pa[p] = v;
        }
    };
    auto loadW = [&](int kt) {
#pragma unroll
        for (int q = 0; q < WREG; q++) {
            int idx = tid + q * 256;          // float4 units
            int k   = idx / (OUT / 4);
            int c4  = idx % (OUT / 4);
            pw[q] = *(const float4*)&W[(size_t)(kt + k) * OUT + c4 * 4];
        }
    };

    loadA(0);
    loadW(0);

    for (int s = 0; s < NSTAGE; s++) {
        // commit prefetched tiles to smem
#pragma unroll
        for (int p = 0; p < 4; p++)
            *(float4*)&As[ar[p]][akc[p] * 4] = pa[p];
#pragma unroll
        for (int q = 0; q < WREG; q++) {
            int idx = tid + q * 256;
            int k   = idx / (OUT / 4);
            int c4  = idx % (OUT / 4);
            *(float4*)&Ws[k][c4 * 4] = pw[q];
        }
        __syncthreads();

        if (s + 1 < NSTAGE) {                 // overlap next-tile LDG with compute
            loadA((s + 1) * BK);
            loadW((s + 1) * BK);
        }

#pragma unroll
        for (int k = 0; k < BK; k++) {
            unsigned long long bp[NP];
            {
                float4 b0 = *(const float4*)&Ws[k][tx * TN];
                bp[0] = pack2(b0.x, b0.y);
                bp[1] = pack2(b0.z, b0.w);
                if constexpr (NP == 4) {
                    float4 b1 = *(const float4*)&Ws[k][tx * TN + 4];
                    bp[2] = pack2(b1.x, b1.y);
                    bp[3] = pack2(b1.z, b1.w);
                }
            }
#pragma unroll
            for (int i = 0; i < 8; i++) {
                float a = As[B + i][k];
                unsigned long long aa = pack2(a, a);
#pragma unroll
                for (int j = 0; j < NP; j++)
                    acc[i][j] = fma2(aa, bp[j], acc[i][j]);
            }
        }
        __syncthreads();
    }

    // ---- epilogue ----
    float bv[TN];
#pragma unroll
    for (int j = 0; j < TN; j++) bv[j] = bias[tx * TN + j];

#pragma unroll
    for (int i = 0; i < 8; i++) {
        int grow = row0 + B + i;
        if (grow >= n) continue;
#pragma unroll
        for (int j = 0; j < NP; j++) {
            float2 v = unpack2(acc[i][j]);
            v.x += bv[2 * j];
            v.y += bv[2 * j + 1];
            if (RELU) { v.x = fmaxf(v.x, 0.f); v.y = fmaxf(v.y, 0.f); }
            int c = tx * TN + 2 * j;
            if constexpr (HALF_OUT) {
                __half2* dst2 = (__half2*)&Ch[(size_t)grow * OUT + c];
                *dst2 = __floats2half2_rn(v.x, v.y);
            } else {
                *(float2*)&Cf[(size_t)grow * OUT + c] = v;
            }
        }
    }
}

// ---------------- head: out = relu(x2 @ Wl1 + bl1) @ Wl2 + bl2 ----------------
__global__ void head_kernel(const float* __restrict__ x2,
                            const float* __restrict__ Wl1,
                            const float* __restrict__ bl1,
                            const float* __restrict__ Wl2,
                            const float* __restrict__ bl2,
                            float* __restrict__ out, int n)
{
    int gtid = blockIdx.x * blockDim.x + threadIdx.x;
    int row  = gtid >> 5;
    int lane = gtid & 31;
    if (row >= n) return;

    const float* xr = x2 + (size_t)row * 64;
    float acc = 0.f;
#pragma unroll
    for (int k = 0; k < 64; k++)
        acc = fmaf(__ldg(&xr[k]), __ldg(&Wl1[k * 32 + lane]), acc);
    float h = fmaxf(acc + __ldg(&bl1[lane]), 0.f);
    float p = h * __ldg(&Wl2[lane]);
#pragma unroll
    for (int off = 16; off; off >>= 1)
        p += __shfl_down_sync(0xffffffffu, p, off);
    if (lane == 0) out[row] = p + __ldg(&bl2[0]);
}

// ---------------- launch ----------------
extern "C" void kernel_launch(void* const* d_in, const int* in_sizes, int n_in,
                              void* d_out, int out_size)
{
    const float* x    = (const float*)d_in[0];
    const int*   ei   = (const int*)  d_in[1];
    const float* W1a  = (const float*)d_in[3];
    const float* b1a  = (const float*)d_in[4];
    const float* W1b  = (const float*)d_in[5];
    const float* b1b  = (const float*)d_in[6];
    const float* W2a  = (const float*)d_in[7];
    const float* b2a  = (const float*)d_in[8];
    const float* W2b  = (const float*)d_in[9];
    const float* b2b  = (const float*)d_in[10];
    const float* Wl1  = (const float*)d_in[11];
    const float* bl1  = (const float*)d_in[12];
    const float* Wl2  = (const float*)d_in[13];
    const float* bl2  = (const float*)d_in[14];
    float* out = (float*)d_out;

    const int N = in_sizes[0] / INDIM;
    const int E = in_sizes[1] / 2;
    const int* src = ei;
    const int* dst = ei + E;

    __half *h2;
    float *m, *x1, *x2, *deg;
    cudaGetSymbolAddress((void**)&h2,  g_h2);
    cudaGetSymbolAddress((void**)&m,   g_m);
    cudaGetSymbolAddress((void**)&x1,  g_x1);
    cudaGetSymbolAddress((void**)&x2,  g_x2);
    cudaGetSymbolAddress((void**)&deg, g_deg);

    const int T = 256;
    auto blocks = [](long long work, int t) { return (int)((work + t - 1) / t); };
    const int gemm_grid = blocks(N, 128);

    // degree (shared by both layers)
    zero4_kernel<<<blocks((N + 3) / 4, T), T>>>((float4*)deg, (N + 3) / 4);
    degree_kernel<<<blocks(E, T), T>>>(dst, deg, E);
    invdeg_kernel<<<blocks(N, T), T>>>(deg, N);

    // ---- layer 1 ----
    zero4_kernel<<<blocks((long long)N * 16, T), T>>>((float4*)m, N * 16);
    gemm_cat4<256, 0, 64, false, true><<<gemm_grid, 256>>>(x, nullptr, nullptr, W1a, b1a, nullptr, h2, N);
    scatter64_h_kernel<<<blocks((long long)E * 16, T), T>>>((const uint2*)h2, src, dst, (float4*)m, E);
    gemm_cat4<256, 64, 128, true, false><<<gemm_grid, 256>>>(x, m, deg, W1b, b1b, x1, nullptr, N);

    // ---- layer 2 ----
    zero4_kernel<<<blocks((long long)N * 16, T), T>>>((float4*)m, N * 16);
    gemm_cat4<128, 0, 64, false, true><<<gemm_grid, 256>>>(x1, nullptr, nullptr, W2a, b2a, nullptr, h2, N);
    scatter64_h_kernel<<<blocks((long long)E * 16, T), T>>>((const uint2*)h2, src, dst, (float4*)m, E);
    gemm_cat4<128, 64, 64, true, false><<<gemm_grid, 256>>>(x1, m, deg, W2b, b2b, x2, nullptr, N);

    // ---- head ----
    head_kernel<<<blocks((long long)N * 32, T), T>>>(x2, Wl1, bl1, Wl2, bl2, out, N);
}